// round 2
// baseline (speedup 1.0000x reference)
#include <cuda_runtime.h>
#include <math.h>

#define Bn   8
#define Cc   256
#define Ls   2048
#define NH   4
#define DH   32
#define HID  128
#define NQKV 384   // stacked Q(128) K(128) V(128) rows

// Scratch (allocation-free rule: __device__ globals)
__device__ float g_qkv[(size_t)Bn * NQKV * Ls];   // [B][384][L], 25.2 MB
__device__ float g_att[(size_t)Bn * HID * Ls];    // [B][128][L], 8.4 MB

// ---------------------------------------------------------------------------
// Kernel 1: channel LayerNorm (dim C) fused with QKV projection.
// Block: 256 threads, handles one batch x 64 L-columns.
// Output: g_qkv[b][n][l],  n = h*32+d for Q rows 0..127, K 128..255, V 256..383
// ---------------------------------------------------------------------------
__global__ __launch_bounds__(256) void k_ln_qkv(
    const float* __restrict__ x, const float* __restrict__ gw,
    const float* __restrict__ bw,
    const float* __restrict__ Wq, const float* __restrict__ Wk,
    const float* __restrict__ Wv)
{
    extern __shared__ float sm[];
    float* xs    = sm;                 // [256][65]
    float* ws    = xs + 256 * 65;      // [64][257]
    float* red   = ws + 64 * 257;      // 512
    float* stats = red + 512;          // mean[64], rstd[64]

    const int tid = threadIdx.x;
    const int b   = blockIdx.y;
    const int l0  = blockIdx.x * 64;
    const float* xb = x + ((size_t)b * Cc) * Ls + l0;

    // load x tile [256 c][64 l]
    #pragma unroll
    for (int k = 0; k < 64; k++) {
        int idx = tid + k * 256;
        int c = idx >> 6, ll = idx & 63;
        xs[c * 65 + ll] = xb[(size_t)c * Ls + ll];
    }
    __syncthreads();

    // per-column mean/var (biased) over C=256; 4 partials per column
    {
        int ll = tid & 63, part = tid >> 6;
        float s = 0.f, s2 = 0.f;
        for (int c = part; c < 256; c += 4) {
            float v = xs[c * 65 + ll];
            s += v; s2 += v * v;
        }
        red[part * 64 + ll]       = s;
        red[256 + part * 64 + ll] = s2;
    }
    __syncthreads();
    if (tid < 64) {
        float ts  = red[tid] + red[64 + tid] + red[128 + tid] + red[192 + tid];
        float ts2 = red[256 + tid] + red[320 + tid] + red[384 + tid] + red[448 + tid];
        float mean = ts * (1.f / 256.f);
        float var  = ts2 * (1.f / 256.f) - mean * mean;
        stats[tid]      = mean;
        stats[64 + tid] = rsqrtf(var + 1e-5f);
    }
    __syncthreads();

    // normalize in place (+ affine g,b)
    #pragma unroll
    for (int k = 0; k < 64; k++) {
        int idx = tid + k * 256;
        int c = idx >> 6, ll = idx & 63;
        float m = stats[ll], r = stats[64 + ll];
        xs[c * 65 + ll] = (xs[c * 65 + ll] - m) * r * gw[c] + bw[c];
    }
    __syncthreads();

    // GEMM: out[n][l] = sum_c W[n][c] * xs[c][l], n in 6 chunks of 64
    const int tx = tid & 15, ty = tid >> 4;   // l-group, n-group
    for (int nc = 0; nc < 6; nc++) {
        #pragma unroll
        for (int k = 0; k < 64; k++) {
            int idx = tid + k * 256;
            int nn = idx >> 8, c = idx & 255;
            int n = nc * 64 + nn;
            const float* wrow;
            if (n < 128)      wrow = Wq + (size_t)n * 256;
            else if (n < 256) wrow = Wk + (size_t)(n - 128) * 256;
            else              wrow = Wv + (size_t)(n - 256) * 256;
            ws[nn * 257 + c] = wrow[c];
        }
        __syncthreads();

        float acc[4][4] = {};
        #pragma unroll 4
        for (int c = 0; c < 256; c++) {
            float a0 = xs[c * 65 + tx * 4 + 0];
            float a1 = xs[c * 65 + tx * 4 + 1];
            float a2 = xs[c * 65 + tx * 4 + 2];
            float a3 = xs[c * 65 + tx * 4 + 3];
            #pragma unroll
            for (int j = 0; j < 4; j++) {
                float w = ws[(ty * 4 + j) * 257 + c];
                acc[j][0] += w * a0; acc[j][1] += w * a1;
                acc[j][2] += w * a2; acc[j][3] += w * a3;
            }
        }
        float* outb = g_qkv + ((size_t)b * NQKV + nc * 64) * Ls + l0;
        #pragma unroll
        for (int j = 0; j < 4; j++) {
            float4 v = make_float4(acc[j][0], acc[j][1], acc[j][2], acc[j][3]);
            *(float4*)(outb + (size_t)(ty * 4 + j) * Ls + tx * 4) = v;
        }
        __syncthreads();
    }
}

// ---------------------------------------------------------------------------
// Kernel 2: flash attention per (b, h, 64-query tile). Block = 256 threads.
// Quad of 4 lanes owns one query i; j interleaved across quad (j = q + 4*jj).
// ---------------------------------------------------------------------------
__global__ __launch_bounds__(256) void k_attn()
{
    __shared__ float Ks[32 * 64];
    __shared__ float Vs[32 * 64];

    const int tid = threadIdx.x;
    const int b = blockIdx.z, h = blockIdx.y;
    const int i0 = blockIdx.x * 64;
    const int q  = tid & 3;        // quad lane
    const int il = tid >> 2;       // query within tile (0..63)

    const float* Qg = g_qkv + ((size_t)b * NQKV + h * DH) * Ls;
    const float* Kg = g_qkv + ((size_t)b * NQKV + HID + h * DH) * Ls;
    const float* Vg = g_qkv + ((size_t)b * NQKV + 2 * HID + h * DH) * Ls;

    const float scale = 0.1767766952966369f;  // 32^-0.5
    float Qr[32];
    #pragma unroll
    for (int d = 0; d < 32; d++)
        Qr[d] = Qg[(size_t)d * Ls + i0 + il] * scale;

    float acc[32];
    #pragma unroll
    for (int d = 0; d < 32; d++) acc[d] = 0.f;
    float mrun = -1e30f, lrun = 0.f;

    // staging indices: 256 threads load 2048 floats per tile via float4
    const int sd  = tid >> 4;         // d row 0..15 (x2)
    const int sj4 = (tid & 15) * 4;   // jl base

    for (int j0 = 0; j0 < Ls; j0 += 64) {
        __syncthreads();
        {
            const float* kp0 = Kg + (size_t)sd * Ls + j0 + sj4;
            const float* kp1 = Kg + (size_t)(sd + 16) * Ls + j0 + sj4;
            const float* vp0 = Vg + (size_t)sd * Ls + j0 + sj4;
            const float* vp1 = Vg + (size_t)(sd + 16) * Ls + j0 + sj4;
            *(float4*)(Ks + sd * 64 + sj4)        = *(const float4*)kp0;
            *(float4*)(Ks + (sd + 16) * 64 + sj4) = *(const float4*)kp1;
            *(float4*)(Vs + sd * 64 + sj4)        = *(const float4*)vp0;
            *(float4*)(Vs + (sd + 16) * 64 + sj4) = *(const float4*)vp1;
        }
        __syncthreads();

        float s[16];
        #pragma unroll
        for (int jj = 0; jj < 16; jj++) {
            float a = 0.f;
            #pragma unroll
            for (int d = 0; d < 32; d++)
                a += Qr[d] * Ks[d * 64 + q + jj * 4];
            s[jj] = a;
        }
        float tmax = s[0];
        #pragma unroll
        for (int jj = 1; jj < 16; jj++) tmax = fmaxf(tmax, s[jj]);
        tmax = fmaxf(tmax, __shfl_xor_sync(0xffffffffu, tmax, 1));
        tmax = fmaxf(tmax, __shfl_xor_sync(0xffffffffu, tmax, 2));

        float nm   = fmaxf(mrun, tmax);
        float corr = __expf(mrun - nm);
        float ps   = 0.f;
        #pragma unroll
        for (int jj = 0; jj < 16; jj++) { s[jj] = __expf(s[jj] - nm); ps += s[jj]; }
        ps += __shfl_xor_sync(0xffffffffu, ps, 1);
        ps += __shfl_xor_sync(0xffffffffu, ps, 2);
        lrun = lrun * corr + ps;
        mrun = nm;

        #pragma unroll
        for (int d = 0; d < 32; d++) acc[d] *= corr;
        #pragma unroll
        for (int jj = 0; jj < 16; jj++) {
            float p = s[jj];
            #pragma unroll
            for (int d = 0; d < 32; d++)
                acc[d] += p * Vs[d * 64 + q + jj * 4];
        }
    }

    // reduce partial O over the quad; all 4 lanes end with full sums
    #pragma unroll
    for (int d = 0; d < 32; d++) {
        acc[d] += __shfl_xor_sync(0xffffffffu, acc[d], 1);
        acc[d] += __shfl_xor_sync(0xffffffffu, acc[d], 2);
    }
    if (q == 0) {
        float inv = 1.f / lrun;
        float* Og = g_att + ((size_t)b * HID + h * DH) * Ls + i0 + il;
        #pragma unroll
        for (int d = 0; d < 32; d++)
            Og[(size_t)d * Ls] = acc[d] * inv;
    }
}

// ---------------------------------------------------------------------------
// Kernel 3: y = Wo @ att + bo + x (residual).  Block: batch x 64 L-columns.
// ---------------------------------------------------------------------------
__global__ __launch_bounds__(256) void k_out(
    const float* __restrict__ Wo, const float* __restrict__ bo,
    const float* __restrict__ x, float* __restrict__ y)
{
    extern __shared__ float sm[];
    float* Ot = sm;              // [128][65]
    float* ws = Ot + 128 * 65;   // [64][129]

    const int tid = threadIdx.x;
    const int b = blockIdx.y;
    const int l0 = blockIdx.x * 64;
    const float* Ob = g_att + ((size_t)b * HID) * Ls + l0;

    #pragma unroll
    for (int k = 0; k < 32; k++) {
        int idx = tid + k * 256;
        int n = idx >> 6, ll = idx & 63;
        Ot[n * 65 + ll] = Ob[(size_t)n * Ls + ll];
    }
    __syncthreads();

    const int tx = tid & 15, ty = tid >> 4;
    for (int oc = 0; oc < 4; oc++) {
        #pragma unroll
        for (int k = 0; k < 32; k++) {
            int idx = tid + k * 256;
            int nn = idx >> 7, c = idx & 127;
            ws[nn * 129 + c] = Wo[(size_t)(oc * 64 + nn) * 128 + c];
        }
        __syncthreads();

        float acc[4][4] = {};
        #pragma unroll 4
        for (int c = 0; c < 128; c++) {
            float a0 = Ot[c * 65 + tx * 4 + 0];
            float a1 = Ot[c * 65 + tx * 4 + 1];
            float a2 = Ot[c * 65 + tx * 4 + 2];
            float a3 = Ot[c * 65 + tx * 4 + 3];
            #pragma unroll
            for (int j = 0; j < 4; j++) {
                float w = ws[(ty * 4 + j) * 129 + c];
                acc[j][0] += w * a0; acc[j][1] += w * a1;
                acc[j][2] += w * a2; acc[j][3] += w * a3;
            }
        }

        const float* xb = x + ((size_t)b * Cc + oc * 64) * Ls + l0;
        float*       yb = y + ((size_t)b * Cc + oc * 64) * Ls + l0;
        #pragma unroll
        for (int j = 0; j < 4; j++) {
            int o = oc * 64 + ty * 4 + j;
            float bias = bo[o];
            size_t off = (size_t)(ty * 4 + j) * Ls + tx * 4;
            float4 xr = *(const float4*)(xb + off);
            float4 v  = make_float4(acc[j][0] + bias + xr.x,
                                    acc[j][1] + bias + xr.y,
                                    acc[j][2] + bias + xr.z,
                                    acc[j][3] + bias + xr.w);
            *(float4*)(yb + off) = v;
        }
        __syncthreads();
    }
}

// ---------------------------------------------------------------------------
extern "C" void kernel_launch(void* const* d_in, const int* in_sizes, int n_in,
                              void* d_out, int out_size)
{
    const float* x  = (const float*)d_in[0];
    const float* gw = (const float*)d_in[1];
    const float* bw = (const float*)d_in[2];
    const float* Wq = (const float*)d_in[3];
    const float* Wk = (const float*)d_in[4];
    const float* Wv = (const float*)d_in[5];
    const float* Wo = (const float*)d_in[6];
    const float* bo = (const float*)d_in[7];
    float* y = (float*)d_out;

    const int smem1 = (256 * 65 + 64 * 257 + 512 + 128) * sizeof(float); // ~132 KB
    const int smem3 = (128 * 65 + 64 * 129) * sizeof(float);             // ~66 KB
    cudaFuncSetAttribute(k_ln_qkv, cudaFuncAttributeMaxDynamicSharedMemorySize, smem1);
    cudaFuncSetAttribute(k_out,    cudaFuncAttributeMaxDynamicSharedMemorySize, smem3);

    k_ln_qkv<<<dim3(32, 8), 256, smem1>>>(x, gw, bw, Wq, Wk, Wv);
    k_attn  <<<dim3(32, 4, 8), 256>>>();
    k_out   <<<dim3(32, 8), 256, smem3>>>(Wo, bo, x, y);
}